// round 11
// baseline (speedup 1.0000x reference)
#include <cuda_runtime.h>
#include <cstdint>

#define HID    128
#define NOUT   4096
#define NBLK   16                 // one 16-CTA cluster
#define SLICE  (NOUT / NBLK)      // 256 columns per CTA
#define NB1    256                // blocks for xW1 stage-1
#define ROWS1  256                // rows per block in stage-1
#define EPT    512                // threads in persistent kernel
#define RPITCH 260                // padded redA pitch (floats), 16B-aligned rows

// ---- global scratch ----
__device__ float g_xw1_partial[NB1][HID];

__device__ __forceinline__ float clip01(float v) { return fminf(fmaxf(v, 0.f), 1.f); }

__device__ __forceinline__ uint32_t smem_u32(const void* p) {
    return (uint32_t)__cvta_generic_to_shared(p);
}
__device__ __forceinline__ uint32_t mapa_u32(uint32_t addr, int rank) {
    uint32_t r;
    asm("mapa.shared::cluster.u32 %0, %1, %2;" : "=r"(r) : "r"(addr), "r"(rank));
    return r;
}
__device__ __forceinline__ unsigned long long pk2(float lo, float hi) {
    unsigned long long r;
    asm("mov.b64 %0, {%1, %2};" : "=l"(r) : "f"(lo), "f"(hi));
    return r;
}
__device__ __forceinline__ void upk2(unsigned long long v, float& lo, float& hi) {
    asm("mov.b64 {%0, %1}, %2;" : "=f"(lo), "=f"(hi) : "l"(v));
}
__device__ __forceinline__ unsigned long long fma2(unsigned long long a,
                                                   unsigned long long b,
                                                   unsigned long long c) {
    unsigned long long d;
    asm("fma.rn.f32x2 %0, %1, %2, %3;" : "=l"(d) : "l"(a), "l"(b), "l"(c));
    return d;
}
__device__ __forceinline__ void st_async_b64(uint32_t raddr, unsigned long long val,
                                             uint32_t rmbar) {
    asm volatile(
        "st.async.shared::cluster.mbarrier::complete_tx::bytes.u64 [%0], %1, [%2];"
        :: "r"(raddr), "l"(val), "r"(rmbar) : "memory");
}
__device__ __forceinline__ void mbar_init(uint32_t mbar, uint32_t cnt) {
    asm volatile("mbarrier.init.shared.b64 [%0], %1;" :: "r"(mbar), "r"(cnt) : "memory");
}
__device__ __forceinline__ void mbar_expect_tx(uint32_t mbar, uint32_t bytes) {
    asm volatile("mbarrier.arrive.expect_tx.shared.b64 _, [%0], %1;"
                 :: "r"(mbar), "r"(bytes) : "memory");
}
__device__ __forceinline__ void mbar_wait(uint32_t mbar, uint32_t parity) {
    asm volatile(
        "{\n\t.reg .pred P1;\n\t"
        "WAIT_%=: \n\t"
        "mbarrier.try_wait.parity.acquire.cta.shared::cta.b64 P1, [%0], %1, 0x989680;\n\t"
        "@P1 bra.uni DONE_%=;\n\t"
        "bra.uni WAIT_%=;\n\t"
        "DONE_%=: \n\t}"
        :: "r"(mbar), "r"(parity) : "memory");
}
__device__ __forceinline__ void cluster_sync() {
    asm volatile("barrier.cluster.arrive.aligned;" ::: "memory");
    asm volatile("barrier.cluster.wait.aligned;" ::: "memory");
}

// Stage 1 of xW1 = clip(x) @ W1
__global__ void __launch_bounds__(HID) xw1_partial_kernel(
    const float* __restrict__ x, const float* __restrict__ W1)
{
    int b = blockIdx.x;
    int k = threadIdx.x;
    const float* W1p = W1 + (size_t)b * ROWS1 * HID + k;
    const float* xp  = x  + (size_t)b * ROWS1;
    float a0 = 0.f, a1 = 0.f, a2 = 0.f, a3 = 0.f;
#pragma unroll 8
    for (int r = 0; r < ROWS1; r += 4) {
        a0 = fmaf(clip01(xp[r + 0]), W1p[(size_t)(r + 0) * HID], a0);
        a1 = fmaf(clip01(xp[r + 1]), W1p[(size_t)(r + 1) * HID], a1);
        a2 = fmaf(clip01(xp[r + 2]), W1p[(size_t)(r + 2) * HID], a2);
        a3 = fmaf(clip01(xp[r + 3]), W1p[(size_t)(r + 3) * HID], a3);
    }
    g_xw1_partial[b][k] = (a0 + a1) + (a2 + a3);
}

// Persistent cluster kernel: 16 CTAs, register-resident W2, DSMEM exchange.
__global__ void __launch_bounds__(EPT, 1) ep_kernel(
    const float* __restrict__ W2,
    const float* __restrict__ b_h,
    const float* __restrict__ b_out,
    const float* __restrict__ h0,
    const float* __restrict__ o0,
    const int*   __restrict__ n_iter_p,
    const float* __restrict__ eps_p,
    float*       __restrict__ out)
{
    __shared__ __align__(16) float redA[16][RPITCH];      // pass-A partials
    __shared__ __align__(16) float rh_s[HID];
    __shared__ __align__(16) float ro_s[SLICE];
    __shared__ __align__(16) float buf[2][NBLK][HID];     // exchange buffers
    __shared__ __align__(8)  unsigned long long mbar[2];

    const int tid  = threadIdx.x;
    const int b    = blockIdx.x;          // == cluster rank (grid == 1 cluster)
    const int wid  = tid >> 5;            // 0..15 : row tile (rows wid*8..+8)
    const int lane = tid & 31;            // col groups lane*4 and 128+lane*4

    const uint32_t buf_u32  = smem_u32(&buf[0][0][0]);
    const uint32_t mbar_u32 = smem_u32(&mbar[0]);
    const uint32_t PBYTES   = (uint32_t)NBLK * HID * 4;   // parity buffer stride

    int n_iter = *n_iter_p;
    if (n_iter <= 0 || n_iter > 1000000)
        n_iter = (int)(*reinterpret_cast<const float*>(n_iter_p));
    const float eps = *eps_p;

    if (tid == 0) { mbar_init(mbar_u32, 1); mbar_init(mbar_u32 + 8, 1); }

    // ---- load + pack this thread's 8x8 W2 tile (conflict-free col mapping) ----
    unsigned long long wp[8][4];
#pragma unroll
    for (int r = 0; r < 8; r++) {
        const float* rowp = W2 + (size_t)(wid * 8 + r) * NOUT + (size_t)b * SLICE;
        float4 u = *reinterpret_cast<const float4*>(rowp + lane * 4);
        float4 v = *reinterpret_cast<const float4*>(rowp + 128 + lane * 4);
        wp[r][0] = pk2(u.x, u.y);
        wp[r][1] = pk2(u.z, u.w);
        wp[r][2] = pk2(v.x, v.y);
        wp[r][3] = pk2(v.z, v.w);
    }

    // ---- hoisted exchange addressing (2 sends/lane, b64 row pairs) ----
    const int rp = (((lane >> 4) & 1) << 1) | ((lane >> 3) & 1);   // row-pair in tile
    const int rbit0 = (lane >> 2) & 1;                             // row parity
    uint32_t ad_peer[2], mb_peer[2];
    {
        uint32_t lofs = buf_u32 + (uint32_t)(((b * HID) + wid * 8 + rp * 2) * 4);
#pragma unroll
        for (int g = 0; g < 2; g++) {
            int peer = ((lane & 3) << 2) | (rbit0 << 1) | g;
            ad_peer[g] = mapa_u32(lofs, peer);
            mb_peer[g] = mapa_u32(mbar_u32, peer);
        }
    }

    // ---- state init (warp-specialized ownership) ----
    float o_v = 0.f, mo = 0.f, vo = 0.f, bo = 0.f;                 // tid < 256
    float h_v = 0.f, mh = 0.f, vh = 0.f, bh_r = 0.f, xw1_r = 0.f;  // tid in [256,384)
    if (tid < SLICE) {
        o_v = o0[(size_t)b * SLICE + tid];
        bo  = b_out[(size_t)b * SLICE + tid];
        ro_s[tid] = clip01(o_v);
    } else if (tid < SLICE + HID) {
        int i = tid - SLICE;
        float s0 = 0.f, s1 = 0.f, s2 = 0.f, s3 = 0.f;
#pragma unroll 8
        for (int p = 0; p < NB1; p += 4) {
            s0 += g_xw1_partial[p + 0][i];
            s1 += g_xw1_partial[p + 1][i];
            s2 += g_xw1_partial[p + 2][i];
            s3 += g_xw1_partial[p + 3][i];
        }
        xw1_r = (s0 + s1) + (s2 + s3);
        bh_r  = b_h[i];
        h_v   = h0[i];
        rh_s[i] = clip01(h_v);
    }
    __syncthreads();
    cluster_sync();    // all CTAs' mbarriers + state visible before any st.async

    const float B1 = 0.9f, B2 = 0.999f;
    const float OB1 = 1.0f - 0.9f, OB2 = 1.0f - 0.999f;
    const float AEPS = 1e-8f;
    float b1t = 1.f, b2t = 1.f;

    for (int t = 0; t < n_iter; ++t) {
        b1t *= B1; b2t *= B2;
        const float c1 = 1.f / (1.f - b1t);
        const float c2 = 1.f / (1.f - b2t);
        const int p      = t & 1;
        const int parity = (t >> 1) & 1;

        if (tid == 0) mbar_expect_tx(mbar_u32 + p * 8, PBYTES);

        // ===== pass B: row partials, folded butterfly, packed st.async push =====
        {
            const float4 q0 = *reinterpret_cast<const float4*>(ro_s + lane * 4);
            const float4 q1 = *reinterpret_cast<const float4*>(ro_s + 128 + lane * 4);
            const unsigned long long qa = pk2(q0.x, q0.y), qb = pk2(q0.z, q0.w);
            const unsigned long long qc = pk2(q1.x, q1.y), qd = pk2(q1.z, q1.w);
            float rv[8];
#pragma unroll
            for (int r = 0; r < 8; r++) {
                unsigned long long acc = fma2(wp[r][0], qa, 0ull);
                acc = fma2(wp[r][1], qb, acc);
                acc = fma2(wp[r][2], qc, acc);
                acc = fma2(wp[r][3], qd, acc);
                float lo, hi; upk2(acc, lo, hi);
                rv[r] = lo + hi;
            }
            // folded butterfly -> one full row-sum per lane
#pragma unroll
            for (int r = 0; r < 8; r++) rv[r] += __shfl_xor_sync(0xffffffffu, rv[r], 16);
            float v4[4];
#pragma unroll
            for (int j = 0; j < 4; j++) v4[j] = (lane & 16) ? rv[j + 4] : rv[j];
#pragma unroll
            for (int j = 0; j < 4; j++) v4[j] += __shfl_xor_sync(0xffffffffu, v4[j], 8);
            float v2[2];
#pragma unroll
            for (int j = 0; j < 2; j++) v2[j] = (lane & 8) ? v4[j + 2] : v4[j];
#pragma unroll
            for (int j = 0; j < 2; j++) v2[j] += __shfl_xor_sync(0xffffffffu, v2[j], 4);
            float v1 = (lane & 4) ? v2[1] : v2[0];
            v1 += __shfl_xor_sync(0xffffffffu, v1, 2);
            v1 += __shfl_xor_sync(0xffffffffu, v1, 1);

            // pair adjacent rows into one b64, push to 2 peers (16 covered by dups)
            float vpart = __shfl_xor_sync(0xffffffffu, v1, 4);
            unsigned long long pairv = rbit0 ? pk2(vpart, v1) : pk2(v1, vpart);
            const uint32_t poff = (uint32_t)p * PBYTES;
            const uint32_t moff = (uint32_t)p * 8;
            st_async_b64(ad_peer[0] + poff, pairv, mb_peer[0] + moff);
            st_async_b64(ad_peer[1] + poff, pairv, mb_peer[1] + moff);
        }

        // ===== pass A: col partials via packed FFMA2, conflict-free STS =====
        {
            const float4 ha = *reinterpret_cast<const float4*>(rh_s + wid * 8);
            const float4 hb = *reinterpret_cast<const float4*>(rh_s + wid * 8 + 4);
            const float hv[8] = {ha.x, ha.y, ha.z, ha.w, hb.x, hb.y, hb.z, hb.w};
            unsigned long long pa0 = 0ull, pa1 = 0ull, pa2 = 0ull, pa3 = 0ull;
#pragma unroll
            for (int r = 0; r < 8; r++) {
                unsigned long long hp = pk2(hv[r], hv[r]);
                pa0 = fma2(hp, wp[r][0], pa0);
                pa1 = fma2(hp, wp[r][1], pa1);
                pa2 = fma2(hp, wp[r][2], pa2);
                pa3 = fma2(hp, wp[r][3], pa3);
            }
            *reinterpret_cast<ulonglong2*>(&redA[wid][lane * 4])       = make_ulonglong2(pa0, pa1);
            *reinterpret_cast<ulonglong2*>(&redA[wid][128 + lane * 4]) = make_ulonglong2(pa2, pa3);
        }
        __syncthreads();                                   // S2

        if (tid < SLICE) {
            // ----- o path: reduce pass A over the 16 row-tiles, Adam -----
            float g0 = 0.f, g1 = 0.f, g2 = 0.f, g3 = 0.f;
#pragma unroll
            for (int k = 0; k < 16; k += 4) {
                g0 += redA[k + 0][tid];
                g1 += redA[k + 1][tid];
                g2 += redA[k + 2][tid];
                g3 += redA[k + 3][tid];
            }
            float gsum = (g0 + g1) + (g2 + g3);
            float ro   = clip01(o_v);
            float mask = (o_v >= 0.f && o_v <= 1.f) ? 1.f : 0.f;
            float g    = mask * (ro - bo - gsum);
            mo  = B1 * mo + OB1 * g;
            vo  = B2 * vo + OB2 * g * g;
            o_v -= eps * (mo * c1) / (sqrtf(vo * c2) + AEPS);
            ro_s[tid] = clip01(o_v);
        } else if (tid < SLICE + HID) {
            // ----- h path: DSMEM-gathered sum, replicated Adam -----
            int i = tid - SLICE;
            mbar_wait(mbar_u32 + p * 8, (uint32_t)parity);
            float s0 = 0.f, s1 = 0.f, s2 = 0.f, s3 = 0.f;
#pragma unroll
            for (int s = 0; s < NBLK; s += 4) {
                s0 += buf[p][s + 0][i];
                s1 += buf[p][s + 1][i];
                s2 += buf[p][s + 2][i];
                s3 += buf[p][s + 3][i];
            }
            float S    = (s0 + s1) + (s2 + s3);
            float rh   = rh_s[i];
            float mask = (h_v >= 0.f && h_v <= 1.f) ? 1.f : 0.f;
            float g    = mask * (rh - bh_r - xw1_r - S);
            mh  = B1 * mh + OB1 * g;
            vh  = B2 * vh + OB2 * g * g;
            h_v -= eps * (mh * c1) / (sqrtf(vh * c2) + AEPS);
            rh_s[i] = clip01(h_v);
        }
        __syncthreads();                                   // S3
    }

    if (tid < SLICE) out[(size_t)b * SLICE + tid] = o_v;
    cluster_sync();
}

extern "C" void kernel_launch(void* const* d_in, const int* in_sizes, int n_in,
                              void* d_out, int out_size)
{
    (void)in_sizes; (void)n_in; (void)out_size;
    const float* x    = (const float*)d_in[0];
    const float* W1   = (const float*)d_in[1];
    const float* W2   = (const float*)d_in[2];
    // d_in[3] = b_in (unused by the reference dynamics)
    const float* b_h  = (const float*)d_in[4];
    const float* b_o  = (const float*)d_in[5];
    const float* h0   = (const float*)d_in[6];
    const float* o0   = (const float*)d_in[7];
    const int*   nit  = (const int*)d_in[8];
    const float* eps  = (const float*)d_in[9];
    float* out = (float*)d_out;

    xw1_partial_kernel<<<NB1, HID>>>(x, W1);

    cudaFuncSetAttribute(ep_kernel, cudaFuncAttributeNonPortableClusterSizeAllowed, 1);

    cudaLaunchConfig_t cfg = {};
    cfg.gridDim  = dim3(NBLK, 1, 1);
    cfg.blockDim = dim3(EPT, 1, 1);
    cfg.dynamicSmemBytes = 0;
    cfg.stream = 0;
    cudaLaunchAttribute at[1];
    at[0].id = cudaLaunchAttributeClusterDimension;
    at[0].val.clusterDim.x = NBLK;
    at[0].val.clusterDim.y = 1;
    at[0].val.clusterDim.z = 1;
    cfg.attrs = at;
    cfg.numAttrs = 1;
    cudaLaunchKernelEx(&cfg, ep_kernel, W2, b_h, b_o, h0, o0, nit, eps, out);
}